// round 15
// baseline (speedup 1.0000x reference)
#include <cuda_runtime.h>
#include <cuda_fp16.h>
#include <cstdint>

#define B_  2
#define S_  2048
#define D_  1024
#define H_  16
#define HD_ 64
#define SCALE_ 0.125f
#define QS_ 0.180336880f   // SCALE_ * log2(e)

// Scratch (half precision; 10-bit mantissa == tf32 mantissa)
__device__ __half g_xh[(size_t)B_ * S_ * D_];           // x in half
__device__ __half g_q[(size_t)B_ * H_ * S_ * HD_];      // [b,h,s,hd]  (pre-scaled by QS_)
__device__ __half g_k[(size_t)B_ * H_ * S_ * HD_];      // [b,h,s,hd]
__device__ __half g_v[(size_t)B_ * H_ * HD_ * S_];      // [b,h,hd,s]  (transposed!)
__device__ __half g_att[(size_t)B_ * S_ * D_];          // [b,s,D]
__device__ __half g_wqkvt[(size_t)3 * D_ * D_];         // Wqkv^T [3072,1024]
__device__ __half g_wprojt[(size_t)D_ * D_];            // Wproj^T [1024,1024]

__device__ __forceinline__ uint32_t packh2(float a, float b) {
    __half2 h = __floats2half2_rn(a, b);
    return *reinterpret_cast<uint32_t*>(&h);
}
__device__ __forceinline__ uint32_t ex2h2(uint32_t t) {
    uint32_t p;
    asm("ex2.approx.f16x2 %0, %1;" : "=r"(p) : "r"(t));
    return p;
}

// D = A(16x16 f16 row) * B(16x8 f16 col) + D, fp32 accum
__device__ __forceinline__ void mma16(float d[4], const uint32_t a[4], uint32_t b0, uint32_t b1) {
    asm volatile(
        "mma.sync.aligned.m16n8k16.row.col.f32.f16.f16.f32 "
        "{%0,%1,%2,%3},{%4,%5,%6,%7},{%8,%9},{%0,%1,%2,%3};"
        : "+f"(d[0]), "+f"(d[1]), "+f"(d[2]), "+f"(d[3])
        : "r"(a[0]), "r"(a[1]), "r"(a[2]), "r"(a[3]), "r"(b0), "r"(b1));
}

__device__ __forceinline__ void ldsm4(uint32_t r[4], uint32_t addr) {
    asm volatile("ldmatrix.sync.aligned.m8n8.x4.shared.b16 {%0,%1,%2,%3}, [%4];"
                 : "=r"(r[0]), "=r"(r[1]), "=r"(r[2]), "=r"(r[3]) : "r"(addr));
}

__device__ __forceinline__ void cp16(void* dst, const void* src) {
    uint32_t d = (uint32_t)__cvta_generic_to_shared(dst);
    asm volatile("cp.async.ca.shared.global [%0], [%1], 16;" :: "r"(d), "l"(src));
}
#define CP_COMMIT() asm volatile("cp.async.commit_group;" ::: "memory")
#define CP_WAIT1()  asm volatile("cp.async.wait_group 1;" ::: "memory")
#define CP_WAIT0()  asm volatile("cp.async.wait_group 0;" ::: "memory")

// ---------------------------------------------------------------------------
// x fp32 -> half, vectorized
// ---------------------------------------------------------------------------
__global__ __launch_bounds__(256) void x2h_kernel(const float* __restrict__ in,
                                                  __half* __restrict__ out) {
    const size_t i = ((size_t)blockIdx.x * 256 + threadIdx.x) * 8;
    float4 a = *reinterpret_cast<const float4*>(in + i);
    float4 b = *reinterpret_cast<const float4*>(in + i + 4);
    uint4 u = {packh2(a.x, a.y), packh2(a.z, a.w), packh2(b.x, b.y), packh2(b.z, b.w)};
    *reinterpret_cast<uint4*>(out + i) = u;
}

// ---------------------------------------------------------------------------
// Transpose: out[C,R] = half(in[R,C])
// ---------------------------------------------------------------------------
__global__ __launch_bounds__(256) void transpose_kernel(const float* __restrict__ in,
                                                        __half* __restrict__ out,
                                                        int R, int C) {
    __shared__ float t[32][33];
    const int bx = blockIdx.x * 32, by = blockIdx.y * 32;
    for (int i = threadIdx.y; i < 32; i += 8)
        t[i][threadIdx.x] = in[(size_t)(by + i) * C + bx + threadIdx.x];
    __syncthreads();
    for (int i = threadIdx.y; i < 32; i += 8)
        out[(size_t)(bx + i) * R + by + threadIdx.x] = __float2half(t[threadIdx.x][i]);
}

// ---------------------------------------------------------------------------
// fp16 mma GEMM v4: C[M,N] = A[M,1024] @ Bt[N,1024]^T + bias
// 128x256 CTA tile, 256 thr (8 warps 2x4), warp tile 64x64, BK=32,
// 3-stage cp.async ring, one barrier per chunk.
// MODE 0: scatter into g_q/g_k/g_v (Q pre-scaled by QS_, V transposed).
// ---------------------------------------------------------------------------
template <int NTOT, int MODE>
__global__ __launch_bounds__(256) void mma_gemm_h(const __half* __restrict__ A,
                                                  const __half* __restrict__ Bt,
                                                  const float* __restrict__ bias,
                                                  float* __restrict__ Cout) {
    constexpr int K = 1024;
    constexpr int ST = 20;                       // 16 half2 words + 4 pad (80B rows)
    constexpr int A_ST = 128 * ST;               // 2560 words
    constexpr int B_ST = 256 * ST;               // 5120 words
    constexpr int STAGE = A_ST + B_ST;           // 7680 words
    extern __shared__ uint32_t smg[];            // [3][STAGE]

    const int tid = threadIdx.x, lane = tid & 31, w = tid >> 5;
    const int bm = blockIdx.y * 128, bn = blockIdx.x * 256;
    const int wm = (w & 1) * 64, wn = (w >> 1) * 64;
    const int r = lane >> 2;

    const uint32_t smem_base = (uint32_t)__cvta_generic_to_shared(smg);

    auto issue = [&](int k0, int buf) {
        uint32_t* As = smg + buf * STAGE;
        uint32_t* Bs = As + A_ST;
        // A: 128 rows x 32 halfs = 512 x 16B chunks; 2/thread
#pragma unroll
        for (int it = 0; it < 2; it++) {
            const int id = tid + it * 256;
            const int row = id >> 2, q = id & 3;
            cp16(As + row * ST + q * 4, A + (size_t)(bm + row) * K + k0 + q * 8);
        }
        // B: 256 rows x 32 halfs = 1024 x 16B chunks; 4/thread
#pragma unroll
        for (int it = 0; it < 4; it++) {
            const int id = tid + it * 256;
            const int row = id >> 2, q = id & 3;
            cp16(Bs + row * ST + q * 4, Bt + (size_t)(bn + row) * K + k0 + q * 8);
        }
    };

    float acc[4][8][4];
#pragma unroll
    for (int mi = 0; mi < 4; mi++)
#pragma unroll
        for (int ni = 0; ni < 8; ni++)
#pragma unroll
            for (int q = 0; q < 4; q++) acc[mi][ni][q] = 0.0f;

    issue(0, 0);  CP_COMMIT();
    issue(32, 1); CP_COMMIT();

    const int a_row = (lane & 15);
    const int a_wof = (lane >> 4) << 2;
    const int b_row = ((lane >> 4) << 3) + (lane & 7);
    const int b_wof = ((lane >> 3) & 1) << 2;

    constexpr int NC = K / 32;   // 32 chunks
    for (int ch = 0; ch < NC; ch++) {
        CP_WAIT1();              // tile ch arrived (pending: ch+1)
        __syncthreads();         // the ONLY barrier this iteration
        // refill stage (ch+2)%3 == (ch-1)%3: consumed at iter ch-1 -> WAR safe.
        if (ch + 2 < NC) issue((ch + 2) * 32, (ch + 2) % 3);
        CP_COMMIT();

        const int buf = ch % 3;
        const uint32_t a_base = smem_base + (buf * STAGE) * 4;
        const uint32_t b_base = a_base + A_ST * 4;

#pragma unroll
        for (int kg = 0; kg < 2; kg++) {
            const int kw = kg * 8;
            uint32_t af[4][4];
#pragma unroll
            for (int mi = 0; mi < 4; mi++)
                ldsm4(af[mi], a_base + ((wm + mi * 16 + a_row) * ST + kw + a_wof) * 4);
            uint32_t bf[8][2];
#pragma unroll
            for (int p = 0; p < 4; p++) {
                uint32_t bq[4];
                ldsm4(bq, b_base + ((wn + p * 16 + b_row) * ST + kw + b_wof) * 4);
                bf[2 * p][0] = bq[0]; bf[2 * p][1] = bq[1];
                bf[2 * p + 1][0] = bq[2]; bf[2 * p + 1][1] = bq[3];
            }
#pragma unroll
            for (int mi = 0; mi < 4; mi++)
#pragma unroll
                for (int ni = 0; ni < 8; ni++)
                    mma16(acc[mi][ni], af[mi], bf[ni][0], bf[ni][1]);
        }
    }

    // Epilogue
    const int c2 = (lane & 3) * 2;
#pragma unroll
    for (int mi = 0; mi < 4; mi++) {
#pragma unroll
        for (int ni = 0; ni < 8; ni++) {
            const int col = bn + wn + ni * 8 + c2;
            const float bi0 = bias[col], bi1 = bias[col + 1];
#pragma unroll
            for (int half_ = 0; half_ < 2; half_++) {
                const int row = bm + wm + mi * 16 + r + half_ * 8;
                float v0 = acc[mi][ni][half_ * 2 + 0] + bi0;
                float v1 = acc[mi][ni][half_ * 2 + 1] + bi1;
                if (MODE == 0) {
                    const int which = col >> 10;
                    const int d     = col & 1023;
                    const int h     = d >> 6;
                    const int hd    = d & 63;
                    const int b     = row >> 11;
                    const int s     = row & 2047;
                    if (which == 2) {
                        const size_t base = (((size_t)b * H_ + h) * HD_) * S_;
                        g_v[base + (size_t)hd * S_ + s]       = __float2half(v0);
                        g_v[base + (size_t)(hd + 1) * S_ + s] = __float2half(v1);
                    } else {
                        const size_t dst = (((size_t)b * H_ + h) * S_ + s) * HD_ + hd;
                        if (which == 0) { v0 *= QS_; v1 *= QS_; }   // log2-domain scores
                        __half2 hv = __floats2half2_rn(v0, v1);
                        if (which == 0) *reinterpret_cast<__half2*>(g_q + dst) = hv;
                        else            *reinterpret_cast<__half2*>(g_k + dst) = hv;
                    }
                } else {
                    float2 v = {v0, v1};
                    *reinterpret_cast<float2*>(Cout + (size_t)row * NTOT + col) = v;
                }
            }
        }
    }
}

// ---------------------------------------------------------------------------
// Flash attention, fp16 m16n8k16, log2-domain register softmax.
// 3-stage K/V cp.async ring, ONE barrier per tile. (R13, proven)
// ---------------------------------------------------------------------------
__global__ __launch_bounds__(128, 2) void attn_h() {
    constexpr int ST = 36;   // 32 half2 words + 4 pad
    extern __shared__ uint32_t smu[];
    uint32_t* Qs = smu;                       // [128][36]
    uint32_t* Ks = Qs + 128 * ST;             // [3][64][36]
    uint32_t* Vs = Ks + 3 * 64 * ST;          // [3][64][36]  row=d, halves along s

    const int b  = blockIdx.z;
    const int h  = blockIdx.y;
    const int q0 = blockIdx.x * 128;

    const __half* Qg = g_q + (((size_t)b * H_ + h) * S_ + q0) * HD_;
    const __half* Kg = g_k + ((size_t)b * H_ + h) * S_ * HD_;
    const __half* Vg = g_v + ((size_t)b * H_ + h) * HD_ * S_;

    const int tid = threadIdx.x, lane = tid & 31, w = tid >> 5;
    const int wrow = w * 32;
    const int r = lane >> 2, c = lane & 3;
    const int c2 = c * 2;
    const uint32_t ones_b = (r == 0) ? 0x3C003C00u : 0u;   // ones-column B frag

    auto issue_kv = [&](int kt, int buf) {
        uint32_t* Kb = Ks + buf * 64 * ST;
        uint32_t* Vb = Vs + buf * 64 * ST;
#pragma unroll
        for (int it = 0; it < 4; it++) {
            const int slot = tid + it * 128;
            const int row = slot >> 3, ch = slot & 7;
            cp16(Kb + row * ST + ch * 4, Kg + (size_t)(kt + row) * HD_ + ch * 8);
            cp16(Vb + row * ST + ch * 4, Vg + (size_t)row * S_ + kt + ch * 8);
        }
    };

#pragma unroll
    for (int it = 0; it < 8; it++) {
        const int slot = tid + it * 128;
        const int row = slot >> 3, ch = slot & 7;
        cp16(Qs + row * ST + ch * 4, Qg + (size_t)row * HD_ + ch * 8);
    }
    issue_kv(0, 0);
    CP_COMMIT();
    issue_kv(64, 1);
    CP_COMMIT();

    CP_WAIT1();          // Q + tile0 ready
    __syncthreads();

    uint32_t qf[2][4][4];
#pragma unroll
    for (int mi = 0; mi < 2; mi++)
#pragma unroll
        for (int kg = 0; kg < 4; kg++) {
            const int kw = kg * 8;
            qf[mi][kg][0] = Qs[(wrow + mi * 16 + r) * ST + kw + c];
            qf[mi][kg][1] = Qs[(wrow + mi * 16 + 8 + r) * ST + kw + c];
            qf[mi][kg][2] = Qs[(wrow + mi * 16 + r) * ST + kw + c + 4];
            qf[mi][kg][3] = Qs[(wrow + mi * 16 + 8 + r) * ST + kw + c + 4];
        }

    float m[4];
#pragma unroll
    for (int i = 0; i < 4; i++) m[i] = -1e30f;
    float O[2][9][4];   // [..][8] = l accumulator (ones column)
#pragma unroll
    for (int mi = 0; mi < 2; mi++)
#pragma unroll
        for (int ni = 0; ni < 9; ni++)
#pragma unroll
            for (int q = 0; q < 4; q++) O[mi][ni][q] = 0.0f;

    constexpr int NT = S_ / 64;   // 32 tiles
    for (int i = 0; i < NT; i++) {
        CP_WAIT1();              // tile i complete
        __syncthreads();         // the ONLY barrier this iteration
        if (i + 2 < NT) issue_kv((i + 2) * 64, (i + 2) % 3);
        CP_COMMIT();

        const int buf = i % 3;
        const uint32_t* Kb = Ks + buf * 64 * ST;
        const uint32_t* Vb = Vs + buf * 64 * ST;

        // S = Q @ K^T   (already in log2 domain: Q pre-scaled)
        float sf[2][8][4];
#pragma unroll
        for (int mi = 0; mi < 2; mi++)
#pragma unroll
            for (int ni = 0; ni < 8; ni++)
#pragma unroll
                for (int q = 0; q < 4; q++) sf[mi][ni][q] = 0.0f;
#pragma unroll
        for (int kg = 0; kg < 4; kg++) {
            const int kw = kg * 8;
#pragma unroll
            for (int ni = 0; ni < 8; ni++) {
                const uint32_t b0 = Kb[(ni * 8 + r) * ST + kw + c];
                const uint32_t b1 = Kb[(ni * 8 + r) * ST + kw + c + 4];
                mma16(sf[0][ni], qf[0][kg], b0, b1);
                mma16(sf[1][ni], qf[1][kg], b0, b1);
            }
        }

        // log2-domain softmax -> fp16 P fragments directly
        uint32_t pf[2][4][4];
#pragma unroll
        for (int mi = 0; mi < 2; mi++) {
            float mloc0 = -1e30f, mloc1 = -1e30f;
#pragma unroll
            for (int ni = 0; ni < 8; ni++) {
                mloc0 = fmaxf(mloc0, fmaxf(sf[mi][ni][0], sf[mi][ni][1]));
                mloc1 = fmaxf(mloc1, fmaxf(sf[mi][ni][2], sf[mi][ni][3]));
            }
            mloc0 = fmaxf(mloc0, __shfl_xor_sync(0xffffffffu, mloc0, 1));
            mloc0 = fmaxf(mloc0, __shfl_xor_sync(0xffffffffu, mloc0, 2));
            mloc1 = fmaxf(mloc1, __shfl_xor_sync(0xffffffffu, mloc1, 1));
            mloc1 = fmaxf(mloc1, __shfl_xor_sync(0xffffffffu, mloc1, 2));

            const float mnew0 = fmaxf(m[mi * 2 + 0], mloc0);
            const float mnew1 = fmaxf(m[mi * 2 + 1], mloc1);
            const float alpha0 = exp2f(m[mi * 2 + 0] - mnew0);
            const float alpha1 = exp2f(m[mi * 2 + 1] - mnew1);
            m[mi * 2 + 0] = mnew0;
            m[mi * 2 + 1] = mnew1;

#pragma unroll
            for (int kg = 0; kg < 4; kg++) {
                pf[mi][kg][0] = ex2h2(packh2(sf[mi][2 * kg][0] - mnew0, sf[mi][2 * kg][1] - mnew0));
                pf[mi][kg][1] = ex2h2(packh2(sf[mi][2 * kg][2] - mnew1, sf[mi][2 * kg][3] - mnew1));
                pf[mi][kg][2] = ex2h2(packh2(sf[mi][2 * kg + 1][0] - mnew0, sf[mi][2 * kg + 1][1] - mnew0));
                pf[mi][kg][3] = ex2h2(packh2(sf[mi][2 * kg + 1][2] - mnew1, sf[mi][2 * kg + 1][3] - mnew1));
            }

#pragma unroll
            for (int ni = 0; ni < 9; ni++) {
                O[mi][ni][0] *= alpha0; O[mi][ni][1] *= alpha0;
                O[mi][ni][2] *= alpha1; O[mi][ni][3] *= alpha1;
            }
        }

        // O += P @ V  (ni=8 = ones column -> accumulates l)
#pragma unroll
        for (int kg = 0; kg < 4; kg++) {
            const int kw = kg * 8;
#pragma unroll
            for (int ni = 0; ni < 8; ni++) {
                const uint32_t b0 = Vb[(ni * 8 + r) * ST + kw + c];
                const uint32_t b1 = Vb[(ni * 8 + r) * ST + kw + c + 4];
                mma16(O[0][ni], pf[0][kg], b0, b1);
                mma16(O[1][ni], pf[1][kg], b0, b1);
            }
            mma16(O[0][8], pf[0][kg], ones_b, ones_b);
            mma16(O[1][8], pf[1][kg], ones_b, ones_b);
        }
    }

    // Normalize (l lives in O[mi][8][0]/[2] of the c==0 lane of each quad)
#pragma unroll
    for (int mi = 0; mi < 2; mi++) {
        const float l0 = __shfl_sync(0xffffffffu, O[mi][8][0], lane & ~3);
        const float l1 = __shfl_sync(0xffffffffu, O[mi][8][2], lane & ~3);
        const float il0 = 1.0f / l0;
        const float il1 = 1.0f / l1;
#pragma unroll
        for (int ni = 0; ni < 8; ni++) {
            const int col = h * HD_ + ni * 8 + c2;
            const int row0 = q0 + wrow + mi * 16 + r;
            __half2 v0 = __floats2half2_rn(O[mi][ni][0] * il0, O[mi][ni][1] * il0);
            __half2 v1 = __floats2half2_rn(O[mi][ni][2] * il1, O[mi][ni][3] * il1);
            *reinterpret_cast<__half2*>(g_att + ((size_t)b * S_ + row0) * D_ + col)     = v0;
            *reinterpret_cast<__half2*>(g_att + ((size_t)b * S_ + row0 + 8) * D_ + col) = v1;
        }
    }
}

// ---------------------------------------------------------------------------
extern "C" void kernel_launch(void* const* d_in, const int* in_sizes, int n_in,
                              void* d_out, int out_size) {
    (void)in_sizes; (void)n_in; (void)out_size;
    const float* x     = (const float*)d_in[0];
    const float* Wqkv  = (const float*)d_in[1];
    const float* bqkv  = (const float*)d_in[2];
    const float* Wproj = (const float*)d_in[3];
    const float* bproj = (const float*)d_in[4];
    float* out = (float*)d_out;

    __half *xh_dev = nullptr, *att_dev = nullptr, *wqkvt_dev = nullptr, *wprojt_dev = nullptr;
    cudaGetSymbolAddress((void**)&xh_dev,     g_xh);
    cudaGetSymbolAddress((void**)&att_dev,    g_att);
    cudaGetSymbolAddress((void**)&wqkvt_dev,  g_wqkvt);
    cudaGetSymbolAddress((void**)&wprojt_dev, g_wprojt);

    // x -> half
    {
        const size_t n = (size_t)B_ * S_ * D_;
        x2h_kernel<<<(int)(n / (256 * 8)), 256>>>(x, xh_dev);
    }

    // Transpose weights to K-major half [N,K]
    {
        dim3 blk(32, 8);
        transpose_kernel<<<dim3(3 * D_ / 32, D_ / 32), blk>>>(Wqkv, wqkvt_dev, D_, 3 * D_);
        transpose_kernel<<<dim3(D_ / 32, D_ / 32), blk>>>(Wproj, wprojt_dev, D_, D_);
    }

    const int gemm_smem = 3 * (128 + 256) * 20 * 4;   // 92,160 B
    cudaFuncSetAttribute(mma_gemm_h<3 * D_, 0>, cudaFuncAttributeMaxDynamicSharedMemorySize, gemm_smem);
    cudaFuncSetAttribute(mma_gemm_h<D_, 1>,     cudaFuncAttributeMaxDynamicSharedMemorySize, gemm_smem);

    // QKV GEMM (128x256 CTA tile)
    {
        dim3 grid(3 * D_ / 256, (B_ * S_) / 128);
        mma_gemm_h<3 * D_, 0><<<grid, 256, gemm_smem>>>(xh_dev, wqkvt_dev, bqkv, nullptr);
    }

    // Attention (3-stage ring, one barrier/tile)
    {
        const int smem = (128 * 36 + 6 * 64 * 36) * 4;   // 73,728 B
        cudaFuncSetAttribute(attn_h, cudaFuncAttributeMaxDynamicSharedMemorySize, smem);
        dim3 grid(S_ / 128, H_, B_);
        attn_h<<<grid, 128, smem>>>();
    }

    // Output projection
    {
        dim3 grid(D_ / 256, (B_ * S_) / 128);
        mma_gemm_h<D_, 1><<<grid, 256, gemm_smem>>>(att_dev, wprojt_dev, bproj, out);
    }
}

// round 16
// speedup vs baseline: 1.1044x; 1.1044x over previous
#include <cuda_runtime.h>
#include <cuda_fp16.h>
#include <cstdint>

#define B_  2
#define S_  2048
#define D_  1024
#define H_  16
#define HD_ 64
#define SCALE_ 0.125f
#define QS_ 0.180336880f   // SCALE_ * log2(e)

// Scratch (half precision; 10-bit mantissa == tf32 mantissa)
__device__ __half g_xh[(size_t)B_ * S_ * D_];           // x in half
__device__ __half g_q[(size_t)B_ * H_ * S_ * HD_];      // [b,h,s,hd]  (pre-scaled by QS_)
__device__ __half g_k[(size_t)B_ * H_ * S_ * HD_];      // [b,h,s,hd]
__device__ __half g_v[(size_t)B_ * H_ * HD_ * S_];      // [b,h,hd,s]  (transposed!)
__device__ __half g_att[(size_t)B_ * S_ * D_];          // [b,s,D]
__device__ __half g_wqkvh[(size_t)D_ * 3 * D_];         // Wqkv half [1024,3072] (K,N)
__device__ __half g_wprojh[(size_t)D_ * D_];            // Wproj half [1024,1024] (K,N)

__device__ __forceinline__ uint32_t packh2(float a, float b) {
    __half2 h = __floats2half2_rn(a, b);
    return *reinterpret_cast<uint32_t*>(&h);
}
__device__ __forceinline__ uint32_t ex2h2(uint32_t t) {
    uint32_t p;
    asm("ex2.approx.f16x2 %0, %1;" : "=r"(p) : "r"(t));
    return p;
}

// D = A(16x16 f16 row) * B(16x8 f16 col) + D, fp32 accum
__device__ __forceinline__ void mma16(float d[4], const uint32_t a[4], uint32_t b0, uint32_t b1) {
    asm volatile(
        "mma.sync.aligned.m16n8k16.row.col.f32.f16.f16.f32 "
        "{%0,%1,%2,%3},{%4,%5,%6,%7},{%8,%9},{%0,%1,%2,%3};"
        : "+f"(d[0]), "+f"(d[1]), "+f"(d[2]), "+f"(d[3])
        : "r"(a[0]), "r"(a[1]), "r"(a[2]), "r"(a[3]), "r"(b0), "r"(b1));
}

__device__ __forceinline__ void ldsm4(uint32_t r[4], uint32_t addr) {
    asm volatile("ldmatrix.sync.aligned.m8n8.x4.shared.b16 {%0,%1,%2,%3}, [%4];"
                 : "=r"(r[0]), "=r"(r[1]), "=r"(r[2]), "=r"(r[3]) : "r"(addr));
}
__device__ __forceinline__ void ldsm4t(uint32_t r[4], uint32_t addr) {
    asm volatile("ldmatrix.sync.aligned.m8n8.x4.trans.shared.b16 {%0,%1,%2,%3}, [%4];"
                 : "=r"(r[0]), "=r"(r[1]), "=r"(r[2]), "=r"(r[3]) : "r"(addr));
}

__device__ __forceinline__ void cp16(void* dst, const void* src) {
    uint32_t d = (uint32_t)__cvta_generic_to_shared(dst);
    asm volatile("cp.async.ca.shared.global [%0], [%1], 16;" :: "r"(d), "l"(src));
}
#define CP_COMMIT() asm volatile("cp.async.commit_group;" ::: "memory")
#define CP_WAIT1()  asm volatile("cp.async.wait_group 1;" ::: "memory")
#define CP_WAIT0()  asm volatile("cp.async.wait_group 0;" ::: "memory")

// ---------------------------------------------------------------------------
// fp32 -> half, vectorized (used for x, Wqkv, Wproj; layout preserved)
// ---------------------------------------------------------------------------
__global__ __launch_bounds__(256) void x2h_kernel(const float* __restrict__ in,
                                                  __half* __restrict__ out) {
    const size_t i = ((size_t)blockIdx.x * 256 + threadIdx.x) * 8;
    float4 a = *reinterpret_cast<const float4*>(in + i);
    float4 b = *reinterpret_cast<const float4*>(in + i + 4);
    uint4 u = {packh2(a.x, a.y), packh2(a.z, a.w), packh2(b.x, b.y), packh2(b.z, b.w)};
    *reinterpret_cast<uint4*>(out + i) = u;
}

// ---------------------------------------------------------------------------
// fp16 mma GEMM v5: C[M,N] = A[M,1024] @ W[1024,N] + bias   (W K-major [K,N]!)
// 128x128 CTA tile, 128 thr (4 warps 2x2), warp tile 64x64, BK=32.
// 3-stage cp.async ring, ONE barrier per chunk. B frags via ldmatrix.trans.
// A smem: [128 rows][20 words]; B smem: [32 k-rows][68 words] (128 halfs + pad).
// MODE 0: scatter into g_q/g_k/g_v (Q pre-scaled by QS_, V transposed).
// ---------------------------------------------------------------------------
template <int NTOT, int MODE>
__global__ __launch_bounds__(128) void mma_gemm_h(const __half* __restrict__ A,
                                                  const __half* __restrict__ W,
                                                  const float* __restrict__ bias,
                                                  float* __restrict__ Cout) {
    constexpr int K = 1024;
    constexpr int STA = 20;                      // A row pitch (words)
    constexpr int STB = 68;                      // B k-row pitch (words), 68%32=4 -> conflict-free trans
    constexpr int A_WORDS = 128 * STA;           // 2560
    constexpr int B_WORDS = 32 * STB;            // 2176
    constexpr int STAGE = A_WORDS + B_WORDS;     // 4736 words = 18,944 B
    extern __shared__ uint32_t smg[];            // [3][STAGE]

    const int tid = threadIdx.x, lane = tid & 31, w = tid >> 5;
    const int bm = blockIdx.y * 128, bn = blockIdx.x * 128;
    const int wm = (w & 1) * 64, wn = (w >> 1) * 64;
    const int r = lane >> 2;

    const uint32_t smem_base = (uint32_t)__cvta_generic_to_shared(smg);

    auto issue = [&](int k0, int buf) {
        uint32_t* As = smg + buf * STAGE;
        uint32_t* Bs = As + A_WORDS;
        // A: 128 rows x 32 halfs = 512 granules; 4/thread
#pragma unroll
        for (int it = 0; it < 4; it++) {
            const int id = tid + it * 128;
            const int row = id >> 2, q = id & 3;
            cp16(As + row * STA + q * 4, A + (size_t)(bm + row) * K + k0 + q * 8);
        }
        // B: 32 k-rows x 128 halfs = 512 granules; 4/thread
#pragma unroll
        for (int it = 0; it < 4; it++) {
            const int id = tid + it * 128;
            const int row = id >> 4, g = id & 15;   // row=k, g=16B granule along n
            cp16(Bs + row * STB + g * 4, W + (size_t)(k0 + row) * NTOT + bn + g * 8);
        }
    };

    float acc[4][8][4];
#pragma unroll
    for (int mi = 0; mi < 4; mi++)
#pragma unroll
        for (int ni = 0; ni < 8; ni++)
#pragma unroll
            for (int q = 0; q < 4; q++) acc[mi][ni][q] = 0.0f;

    issue(0, 0);  CP_COMMIT();
    issue(32, 1); CP_COMMIT();

    // A-fragment address components
    const int a_row = (lane & 15);
    const int a_wof = (lane >> 4) << 2;
    // B-trans address components: g = lane>>3 selects matrix, lr = lane&7 row-within
    const int bg = lane >> 3, blr = lane & 7;
    const int b_krow_off = (bg & 1) * 8 + blr;          // k within 16-group
    const int b_nhalf_off = (bg >> 1) * 8;              // n within 16-group

    constexpr int NC = K / 32;   // 32 chunks
    for (int ch = 0; ch < NC; ch++) {
        CP_WAIT1();              // chunk ch resident
        __syncthreads();         // the ONLY barrier this iteration
        // refill stage (ch+2)%3 == (ch-1)%3: consumed at iter ch-1 -> WAR safe.
        if (ch + 2 < NC) issue((ch + 2) * 32, (ch + 2) % 3);
        CP_COMMIT();

        const int buf = ch % 3;
        const uint32_t a_base = smem_base + (buf * STAGE) * 4;
        const uint32_t b_base = a_base + A_WORDS * 4;

#pragma unroll
        for (int kg = 0; kg < 2; kg++) {
            const int kw = kg * 8;               // A word offset
            uint32_t af[4][4];
#pragma unroll
            for (int mi = 0; mi < 4; mi++)
                ldsm4(af[mi], a_base + ((wm + mi * 16 + a_row) * STA + kw + a_wof) * 4);
            uint32_t bf[8][2];
#pragma unroll
            for (int p = 0; p < 4; p++) {
                const int krow = kg * 16 + b_krow_off;
                const int nhalf = wn + p * 16 + b_nhalf_off;
                uint32_t bq[4];
                ldsm4t(bq, b_base + (krow * STB + (nhalf >> 1)) * 4);
                bf[2 * p][0] = bq[0]; bf[2 * p][1] = bq[1];
                bf[2 * p + 1][0] = bq[2]; bf[2 * p + 1][1] = bq[3];
            }
#pragma unroll
            for (int mi = 0; mi < 4; mi++)
#pragma unroll
                for (int ni = 0; ni < 8; ni++)
                    mma16(acc[mi][ni], af[mi], bf[ni][0], bf[ni][1]);
        }
    }

    // Epilogue
    const int c2 = (lane & 3) * 2;
#pragma unroll
    for (int mi = 0; mi < 4; mi++) {
#pragma unroll
        for (int ni = 0; ni < 8; ni++) {
            const int col = bn + wn + ni * 8 + c2;
            const float bi0 = bias[col], bi1 = bias[col + 1];
#pragma unroll
            for (int half_ = 0; half_ < 2; half_++) {
                const int row = bm + wm + mi * 16 + r + half_ * 8;
                float v0 = acc[mi][ni][half_ * 2 + 0] + bi0;
                float v1 = acc[mi][ni][half_ * 2 + 1] + bi1;
                if (MODE == 0) {
                    const int which = col >> 10;
                    const int d     = col & 1023;
                    const int h     = d >> 6;
                    const int hd    = d & 63;
                    const int b     = row >> 11;
                    const int s     = row & 2047;
                    if (which == 2) {
                        const size_t base = (((size_t)b * H_ + h) * HD_) * S_;
                        g_v[base + (size_t)hd * S_ + s]       = __float2half(v0);
                        g_v[base + (size_t)(hd + 1) * S_ + s] = __float2half(v1);
                    } else {
                        const size_t dst = (((size_t)b * H_ + h) * S_ + s) * HD_ + hd;
                        if (which == 0) { v0 *= QS_; v1 *= QS_; }   // log2-domain scores
                        __half2 hv = __floats2half2_rn(v0, v1);
                        if (which == 0) *reinterpret_cast<__half2*>(g_q + dst) = hv;
                        else            *reinterpret_cast<__half2*>(g_k + dst) = hv;
                    }
                } else {
                    float2 v = {v0, v1};
                    *reinterpret_cast<float2*>(Cout + (size_t)row * NTOT + col) = v;
                }
            }
        }
    }
}

// ---------------------------------------------------------------------------
// Flash attention, fp16 m16n8k16, log2-domain register softmax.
// 3-stage K/V cp.async ring, ONE barrier per tile. (R13, proven)
// ---------------------------------------------------------------------------
__global__ __launch_bounds__(128, 2) void attn_h() {
    constexpr int ST = 36;   // 32 half2 words + 4 pad
    extern __shared__ uint32_t smu[];
    uint32_t* Qs = smu;                       // [128][36]
    uint32_t* Ks = Qs + 128 * ST;             // [3][64][36]
    uint32_t* Vs = Ks + 3 * 64 * ST;          // [3][64][36]  row=d, halves along s

    const int b  = blockIdx.z;
    const int h  = blockIdx.y;
    const int q0 = blockIdx.x * 128;

    const __half* Qg = g_q + (((size_t)b * H_ + h) * S_ + q0) * HD_;
    const __half* Kg = g_k + ((size_t)b * H_ + h) * S_ * HD_;
    const __half* Vg = g_v + ((size_t)b * H_ + h) * HD_ * S_;

    const int tid = threadIdx.x, lane = tid & 31, w = tid >> 5;
    const int wrow = w * 32;
    const int r = lane >> 2, c = lane & 3;
    const int c2 = c * 2;
    const uint32_t ones_b = (r == 0) ? 0x3C003C00u : 0u;   // ones-column B frag

    auto issue_kv = [&](int kt, int buf) {
        uint32_t* Kb = Ks + buf * 64 * ST;
        uint32_t* Vb = Vs + buf * 64 * ST;
#pragma unroll
        for (int it = 0; it < 4; it++) {
            const int slot = tid + it * 128;
            const int row = slot >> 3, ch = slot & 7;
            cp16(Kb + row * ST + ch * 4, Kg + (size_t)(kt + row) * HD_ + ch * 8);
            cp16(Vb + row * ST + ch * 4, Vg + (size_t)row * S_ + kt + ch * 8);
        }
    };

#pragma unroll
    for (int it = 0; it < 8; it++) {
        const int slot = tid + it * 128;
        const int row = slot >> 3, ch = slot & 7;
        cp16(Qs + row * ST + ch * 4, Qg + (size_t)row * HD_ + ch * 8);
    }
    issue_kv(0, 0);
    CP_COMMIT();
    issue_kv(64, 1);
    CP_COMMIT();

    CP_WAIT1();          // Q + tile0 ready
    __syncthreads();

    uint32_t qf[2][4][4];
#pragma unroll
    for (int mi = 0; mi < 2; mi++)
#pragma unroll
        for (int kg = 0; kg < 4; kg++) {
            const int kw = kg * 8;
            qf[mi][kg][0] = Qs[(wrow + mi * 16 + r) * ST + kw + c];
            qf[mi][kg][1] = Qs[(wrow + mi * 16 + 8 + r) * ST + kw + c];
            qf[mi][kg][2] = Qs[(wrow + mi * 16 + r) * ST + kw + c + 4];
            qf[mi][kg][3] = Qs[(wrow + mi * 16 + 8 + r) * ST + kw + c + 4];
        }

    float m[4];
#pragma unroll
    for (int i = 0; i < 4; i++) m[i] = -1e30f;
    float O[2][9][4];   // [..][8] = l accumulator (ones column)
#pragma unroll
    for (int mi = 0; mi < 2; mi++)
#pragma unroll
        for (int ni = 0; ni < 9; ni++)
#pragma unroll
            for (int q = 0; q < 4; q++) O[mi][ni][q] = 0.0f;

    constexpr int NT = S_ / 64;   // 32 tiles
    for (int i = 0; i < NT; i++) {
        CP_WAIT1();              // tile i complete
        __syncthreads();         // the ONLY barrier this iteration
        if (i + 2 < NT) issue_kv((i + 2) * 64, (i + 2) % 3);
        CP_COMMIT();

        const int buf = i % 3;
        const uint32_t* Kb = Ks + buf * 64 * ST;
        const uint32_t* Vb = Vs + buf * 64 * ST;

        // S = Q @ K^T   (already in log2 domain: Q pre-scaled)
        float sf[2][8][4];
#pragma unroll
        for (int mi = 0; mi < 2; mi++)
#pragma unroll
            for (int ni = 0; ni < 8; ni++)
#pragma unroll
                for (int q = 0; q < 4; q++) sf[mi][ni][q] = 0.0f;
#pragma unroll
        for (int kg = 0; kg < 4; kg++) {
            const int kw = kg * 8;
#pragma unroll
            for (int ni = 0; ni < 8; ni++) {
                const uint32_t b0 = Kb[(ni * 8 + r) * ST + kw + c];
                const uint32_t b1 = Kb[(ni * 8 + r) * ST + kw + c + 4];
                mma16(sf[0][ni], qf[0][kg], b0, b1);
                mma16(sf[1][ni], qf[1][kg], b0, b1);
            }
        }

        // log2-domain softmax -> fp16 P fragments directly
        uint32_t pf[2][4][4];
#pragma unroll
        for (int mi = 0; mi < 2; mi++) {
            float mloc0 = -1e30f, mloc1 = -1e30f;
#pragma unroll
            for (int ni = 0; ni < 8; ni++) {
                mloc0 = fmaxf(mloc0, fmaxf(sf[mi][ni][0], sf[mi][ni][1]));
                mloc1 = fmaxf(mloc1, fmaxf(sf[mi][ni][2], sf[mi][ni][3]));
            }
            mloc0 = fmaxf(mloc0, __shfl_xor_sync(0xffffffffu, mloc0, 1));
            mloc0 = fmaxf(mloc0, __shfl_xor_sync(0xffffffffu, mloc0, 2));
            mloc1 = fmaxf(mloc1, __shfl_xor_sync(0xffffffffu, mloc1, 1));
            mloc1 = fmaxf(mloc1, __shfl_xor_sync(0xffffffffu, mloc1, 2));

            const float mnew0 = fmaxf(m[mi * 2 + 0], mloc0);
            const float mnew1 = fmaxf(m[mi * 2 + 1], mloc1);
            const float alpha0 = exp2f(m[mi * 2 + 0] - mnew0);
            const float alpha1 = exp2f(m[mi * 2 + 1] - mnew1);
            m[mi * 2 + 0] = mnew0;
            m[mi * 2 + 1] = mnew1;

#pragma unroll
            for (int kg = 0; kg < 4; kg++) {
                pf[mi][kg][0] = ex2h2(packh2(sf[mi][2 * kg][0] - mnew0, sf[mi][2 * kg][1] - mnew0));
                pf[mi][kg][1] = ex2h2(packh2(sf[mi][2 * kg][2] - mnew1, sf[mi][2 * kg][3] - mnew1));
                pf[mi][kg][2] = ex2h2(packh2(sf[mi][2 * kg + 1][0] - mnew0, sf[mi][2 * kg + 1][1] - mnew0));
                pf[mi][kg][3] = ex2h2(packh2(sf[mi][2 * kg + 1][2] - mnew1, sf[mi][2 * kg + 1][3] - mnew1));
            }

#pragma unroll
            for (int ni = 0; ni < 9; ni++) {
                O[mi][ni][0] *= alpha0; O[mi][ni][1] *= alpha0;
                O[mi][ni][2] *= alpha1; O[mi][ni][3] *= alpha1;
            }
        }

        // O += P @ V  (ni=8 = ones column -> accumulates l)
#pragma unroll
        for (int kg = 0; kg < 4; kg++) {
            const int kw = kg * 8;
#pragma unroll
            for (int ni = 0; ni < 8; ni++) {
                const uint32_t b0 = Vb[(ni * 8 + r) * ST + kw + c];
                const uint32_t b1 = Vb[(ni * 8 + r) * ST + kw + c + 4];
                mma16(O[0][ni], pf[0][kg], b0, b1);
                mma16(O[1][ni], pf[1][kg], b0, b1);
            }
            mma16(O[0][8], pf[0][kg], ones_b, ones_b);
            mma16(O[1][8], pf[1][kg], ones_b, ones_b);
        }
    }

    // Normalize (l lives in O[mi][8][0]/[2] of the c==0 lane of each quad)
#pragma unroll
    for (int mi = 0; mi < 2; mi++) {
        const float l0 = __shfl_sync(0xffffffffu, O[mi][8][0], lane & ~3);
        const float l1 = __shfl_sync(0xffffffffu, O[mi][8][2], lane & ~3);
        const float il0 = 1.0f / l0;
        const float il1 = 1.0f / l1;
#pragma unroll
        for (int ni = 0; ni < 8; ni++) {
            const int col = h * HD_ + ni * 8 + c2;
            const int row0 = q0 + wrow + mi * 16 + r;
            __half2 v0 = __floats2half2_rn(O[mi][ni][0] * il0, O[mi][ni][1] * il0);
            __half2 v1 = __floats2half2_rn(O[mi][ni][2] * il1, O[mi][ni][3] * il1);
            *reinterpret_cast<__half2*>(g_att + ((size_t)b * S_ + row0) * D_ + col)     = v0;
            *reinterpret_cast<__half2*>(g_att + ((size_t)b * S_ + row0 + 8) * D_ + col) = v1;
        }
    }
}

// ---------------------------------------------------------------------------
extern "C" void kernel_launch(void* const* d_in, const int* in_sizes, int n_in,
                              void* d_out, int out_size) {
    (void)in_sizes; (void)n_in; (void)out_size;
    const float* x     = (const float*)d_in[0];
    const float* Wqkv  = (const float*)d_in[1];
    const float* bqkv  = (const float*)d_in[2];
    const float* Wproj = (const float*)d_in[3];
    const float* bproj = (const float*)d_in[4];
    float* out = (float*)d_out;

    __half *xh_dev = nullptr, *att_dev = nullptr, *wqkvh_dev = nullptr, *wprojh_dev = nullptr;
    cudaGetSymbolAddress((void**)&xh_dev,     g_xh);
    cudaGetSymbolAddress((void**)&att_dev,    g_att);
    cudaGetSymbolAddress((void**)&wqkvh_dev,  g_wqkvh);
    cudaGetSymbolAddress((void**)&wprojh_dev, g_wprojh);

    // fp32 -> half converts (layout preserved; no transposes needed)
    {
        x2h_kernel<<<(int)(((size_t)B_ * S_ * D_) / 2048), 256>>>(x, xh_dev);
        x2h_kernel<<<(int)(((size_t)D_ * 3 * D_) / 2048), 256>>>(Wqkv, wqkvh_dev);
        x2h_kernel<<<(int)(((size_t)D_ * D_) / 2048), 256>>>(Wproj, wprojh_dev);
    }

    const int gemm_smem = 3 * (128 * 20 + 32 * 68) * 4;   // 56,832 B
    cudaFuncSetAttribute(mma_gemm_h<3 * D_, 0>, cudaFuncAttributeMaxDynamicSharedMemorySize, gemm_smem);
    cudaFuncSetAttribute(mma_gemm_h<D_, 1>,     cudaFuncAttributeMaxDynamicSharedMemorySize, gemm_smem);

    // QKV GEMM (128x128 tile, trans-B from [K,N] weights)
    {
        dim3 grid(3 * D_ / 128, (B_ * S_) / 128);
        mma_gemm_h<3 * D_, 0><<<grid, 128, gemm_smem>>>(xh_dev, wqkvh_dev, bqkv, nullptr);
    }

    // Attention (3-stage ring, one barrier/tile)
    {
        const int smem = (128 * 36 + 6 * 64 * 36) * 4;   // 73,728 B
        cudaFuncSetAttribute(attn_h, cudaFuncAttributeMaxDynamicSharedMemorySize, smem);
        dim3 grid(S_ / 128, H_, B_);
        attn_h<<<grid, 128, smem>>>();
    }

    // Output projection
    {
        dim3 grid(D_ / 128, (B_ * S_) / 128);
        mma_gemm_h<D_, 1><<<grid, 128, gemm_smem>>>(att_dev, wprojh_dev, bproj, out);
    }
}

// round 17
// speedup vs baseline: 1.1743x; 1.0633x over previous
#include <cuda_runtime.h>
#include <cuda_fp16.h>
#include <cstdint>

#define B_  2
#define S_  2048
#define D_  1024
#define H_  16
#define HD_ 64
#define SCALE_ 0.125f
#define QS_ 0.180336880f   // SCALE_ * log2(e)

// Scratch (half precision; 10-bit mantissa == tf32 mantissa)
__device__ __half g_xh[(size_t)B_ * S_ * D_];           // x in half
__device__ __half g_q[(size_t)B_ * H_ * S_ * HD_];      // [b,h,s,hd]  (pre-scaled by QS_)
__device__ __half g_k[(size_t)B_ * H_ * S_ * HD_];      // [b,h,s,hd]
__device__ __half g_v[(size_t)B_ * H_ * HD_ * S_];      // [b,h,hd,s]  (transposed!)
__device__ __half g_att[(size_t)B_ * S_ * D_];          // [b,s,D]
__device__ __half g_wqkvh[(size_t)D_ * 3 * D_];         // Wqkv half [1024,3072] (K,N)
__device__ __half g_wprojh[(size_t)D_ * D_];            // Wproj half [1024,1024] (K,N)

__device__ __forceinline__ uint32_t packh2(float a, float b) {
    __half2 h = __floats2half2_rn(a, b);
    return *reinterpret_cast<uint32_t*>(&h);
}
__device__ __forceinline__ uint32_t ex2h2(uint32_t t) {
    uint32_t p;
    asm("ex2.approx.f16x2 %0, %1;" : "=r"(p) : "r"(t));
    return p;
}

// D = A(16x16 f16 row) * B(16x8 f16 col) + D, fp32 accum
__device__ __forceinline__ void mma16(float d[4], const uint32_t a[4], uint32_t b0, uint32_t b1) {
    asm volatile(
        "mma.sync.aligned.m16n8k16.row.col.f32.f16.f16.f32 "
        "{%0,%1,%2,%3},{%4,%5,%6,%7},{%8,%9},{%0,%1,%2,%3};"
        : "+f"(d[0]), "+f"(d[1]), "+f"(d[2]), "+f"(d[3])
        : "r"(a[0]), "r"(a[1]), "r"(a[2]), "r"(a[3]), "r"(b0), "r"(b1));
}

__device__ __forceinline__ void ldsm4(uint32_t r[4], uint32_t addr) {
    asm volatile("ldmatrix.sync.aligned.m8n8.x4.shared.b16 {%0,%1,%2,%3}, [%4];"
                 : "=r"(r[0]), "=r"(r[1]), "=r"(r[2]), "=r"(r[3]) : "r"(addr));
}
__device__ __forceinline__ void ldsm4t(uint32_t r[4], uint32_t addr) {
    asm volatile("ldmatrix.sync.aligned.m8n8.x4.trans.shared.b16 {%0,%1,%2,%3}, [%4];"
                 : "=r"(r[0]), "=r"(r[1]), "=r"(r[2]), "=r"(r[3]) : "r"(addr));
}

__device__ __forceinline__ void cp16(void* dst, const void* src) {
    uint32_t d = (uint32_t)__cvta_generic_to_shared(dst);
    asm volatile("cp.async.ca.shared.global [%0], [%1], 16;" :: "r"(d), "l"(src));
}
#define CP_COMMIT() asm volatile("cp.async.commit_group;" ::: "memory")
#define CP_WAIT1()  asm volatile("cp.async.wait_group 1;" ::: "memory")
#define CP_WAIT0()  asm volatile("cp.async.wait_group 0;" ::: "memory")

// ---------------------------------------------------------------------------
// fp32 -> half, vectorized (used for x, Wqkv, Wproj; layout preserved)
// ---------------------------------------------------------------------------
__global__ __launch_bounds__(256) void x2h_kernel(const float* __restrict__ in,
                                                  __half* __restrict__ out) {
    const size_t i = ((size_t)blockIdx.x * 256 + threadIdx.x) * 8;
    float4 a = *reinterpret_cast<const float4*>(in + i);
    float4 b = *reinterpret_cast<const float4*>(in + i + 4);
    uint4 u = {packh2(a.x, a.y), packh2(a.z, a.w), packh2(b.x, b.y), packh2(b.z, b.w)};
    *reinterpret_cast<uint4*>(out + i) = u;
}

// ---------------------------------------------------------------------------
// fp16 mma GEMM v5 (R16, proven): C[M,N] = A[M,1024] @ W[1024,N] + bias
// 128x128 CTA tile, 128 thr (4 warps 2x2), warp tile 64x64, BK=32.
// 3-stage cp.async ring, ONE barrier per chunk. B frags via ldmatrix.trans.
// MODE 0: scatter into g_q/g_k/g_v (Q pre-scaled by QS_, V transposed).
// ---------------------------------------------------------------------------
template <int NTOT, int MODE>
__global__ __launch_bounds__(128) void mma_gemm_h(const __half* __restrict__ A,
                                                  const __half* __restrict__ W,
                                                  const float* __restrict__ bias,
                                                  float* __restrict__ Cout) {
    constexpr int K = 1024;
    constexpr int STA = 20;
    constexpr int STB = 68;
    constexpr int A_WORDS = 128 * STA;
    constexpr int B_WORDS = 32 * STB;
    constexpr int STAGE = A_WORDS + B_WORDS;
    extern __shared__ uint32_t smg[];

    const int tid = threadIdx.x, lane = tid & 31, w = tid >> 5;
    const int bm = blockIdx.y * 128, bn = blockIdx.x * 128;
    const int wm = (w & 1) * 64, wn = (w >> 1) * 64;
    const int r = lane >> 2;

    const uint32_t smem_base = (uint32_t)__cvta_generic_to_shared(smg);

    auto issue = [&](int k0, int buf) {
        uint32_t* As = smg + buf * STAGE;
        uint32_t* Bs = As + A_WORDS;
#pragma unroll
        for (int it = 0; it < 4; it++) {
            const int id = tid + it * 128;
            const int row = id >> 2, q = id & 3;
            cp16(As + row * STA + q * 4, A + (size_t)(bm + row) * K + k0 + q * 8);
        }
#pragma unroll
        for (int it = 0; it < 4; it++) {
            const int id = tid + it * 128;
            const int row = id >> 4, g = id & 15;
            cp16(Bs + row * STB + g * 4, W + (size_t)(k0 + row) * NTOT + bn + g * 8);
        }
    };

    float acc[4][8][4];
#pragma unroll
    for (int mi = 0; mi < 4; mi++)
#pragma unroll
        for (int ni = 0; ni < 8; ni++)
#pragma unroll
            for (int q = 0; q < 4; q++) acc[mi][ni][q] = 0.0f;

    issue(0, 0);  CP_COMMIT();
    issue(32, 1); CP_COMMIT();

    const int a_row = (lane & 15);
    const int a_wof = (lane >> 4) << 2;
    const int bg = lane >> 3, blr = lane & 7;
    const int b_krow_off = (bg & 1) * 8 + blr;
    const int b_nhalf_off = (bg >> 1) * 8;

    constexpr int NC = K / 32;
    for (int ch = 0; ch < NC; ch++) {
        CP_WAIT1();
        __syncthreads();
        if (ch + 2 < NC) issue((ch + 2) * 32, (ch + 2) % 3);
        CP_COMMIT();

        const int buf = ch % 3;
        const uint32_t a_base = smem_base + (buf * STAGE) * 4;
        const uint32_t b_base = a_base + A_WORDS * 4;

#pragma unroll
        for (int kg = 0; kg < 2; kg++) {
            const int kw = kg * 8;
            uint32_t af[4][4];
#pragma unroll
            for (int mi = 0; mi < 4; mi++)
                ldsm4(af[mi], a_base + ((wm + mi * 16 + a_row) * STA + kw + a_wof) * 4);
            uint32_t bf[8][2];
#pragma unroll
            for (int p = 0; p < 4; p++) {
                const int krow = kg * 16 + b_krow_off;
                const int nhalf = wn + p * 16 + b_nhalf_off;
                uint32_t bq[4];
                ldsm4t(bq, b_base + (krow * STB + (nhalf >> 1)) * 4);
                bf[2 * p][0] = bq[0]; bf[2 * p][1] = bq[1];
                bf[2 * p + 1][0] = bq[2]; bf[2 * p + 1][1] = bq[3];
            }
#pragma unroll
            for (int mi = 0; mi < 4; mi++)
#pragma unroll
                for (int ni = 0; ni < 8; ni++)
                    mma16(acc[mi][ni], af[mi], bf[ni][0], bf[ni][1]);
        }
    }

    // Epilogue
    const int c2 = (lane & 3) * 2;
#pragma unroll
    for (int mi = 0; mi < 4; mi++) {
#pragma unroll
        for (int ni = 0; ni < 8; ni++) {
            const int col = bn + wn + ni * 8 + c2;
            const float bi0 = bias[col], bi1 = bias[col + 1];
#pragma unroll
            for (int half_ = 0; half_ < 2; half_++) {
                const int row = bm + wm + mi * 16 + r + half_ * 8;
                float v0 = acc[mi][ni][half_ * 2 + 0] + bi0;
                float v1 = acc[mi][ni][half_ * 2 + 1] + bi1;
                if (MODE == 0) {
                    const int which = col >> 10;
                    const int d     = col & 1023;
                    const int h     = d >> 6;
                    const int hd    = d & 63;
                    const int b     = row >> 11;
                    const int s     = row & 2047;
                    if (which == 2) {
                        const size_t base = (((size_t)b * H_ + h) * HD_) * S_;
                        g_v[base + (size_t)hd * S_ + s]       = __float2half(v0);
                        g_v[base + (size_t)(hd + 1) * S_ + s] = __float2half(v1);
                    } else {
                        const size_t dst = (((size_t)b * H_ + h) * S_ + s) * HD_ + hd;
                        if (which == 0) { v0 *= QS_; v1 *= QS_; }
                        __half2 hv = __floats2half2_rn(v0, v1);
                        if (which == 0) *reinterpret_cast<__half2*>(g_q + dst) = hv;
                        else            *reinterpret_cast<__half2*>(g_k + dst) = hv;
                    }
                } else {
                    float2 v = {v0, v1};
                    *reinterpret_cast<float2*>(Cout + (size_t)row * NTOT + col) = v;
                }
            }
        }
    }
}

// ---------------------------------------------------------------------------
// Flash attention, fp16 m16n8k16, log2-domain register softmax.
// 3-stage K/V cp.async ring, ONE barrier per tile.
// NEW: K/V B-fragments via ldmatrix.x4 (32 ldsm per tile vs 128 scalar LDS).
// ---------------------------------------------------------------------------
__global__ __launch_bounds__(128, 2) void attn_h() {
    constexpr int ST = 36;   // 32 half2 words + 4 pad
    extern __shared__ uint32_t smu[];
    uint32_t* Qs = smu;                       // [128][36]
    uint32_t* Ks = Qs + 128 * ST;             // [3][64][36]
    uint32_t* Vs = Ks + 3 * 64 * ST;          // [3][64][36]  row=hd, cols along s

    const int b  = blockIdx.z;
    const int h  = blockIdx.y;
    const int q0 = blockIdx.x * 128;

    const __half* Qg = g_q + (((size_t)b * H_ + h) * S_ + q0) * HD_;
    const __half* Kg = g_k + ((size_t)b * H_ + h) * S_ * HD_;
    const __half* Vg = g_v + ((size_t)b * H_ + h) * HD_ * S_;

    const int tid = threadIdx.x, lane = tid & 31, w = tid >> 5;
    const int wrow = w * 32;
    const int r = lane >> 2, c = lane & 3;
    const int c2 = c * 2;
    const uint32_t ones_b = (r == 0) ? 0x3C003C00u : 0u;   // ones-column B frag

    const uint32_t ks_base = (uint32_t)__cvta_generic_to_shared(Ks);
    const uint32_t vs_base = (uint32_t)__cvta_generic_to_shared(Vs);

    auto issue_kv = [&](int kt, int buf) {
        uint32_t* Kb = Ks + buf * 64 * ST;
        uint32_t* Vb = Vs + buf * 64 * ST;
#pragma unroll
        for (int it = 0; it < 4; it++) {
            const int slot = tid + it * 128;
            const int row = slot >> 3, ch = slot & 7;
            cp16(Kb + row * ST + ch * 4, Kg + (size_t)(kt + row) * HD_ + ch * 8);
            cp16(Vb + row * ST + ch * 4, Vg + (size_t)row * S_ + kt + ch * 8);
        }
    };

#pragma unroll
    for (int it = 0; it < 8; it++) {
        const int slot = tid + it * 128;
        const int row = slot >> 3, ch = slot & 7;
        cp16(Qs + row * ST + ch * 4, Qg + (size_t)row * HD_ + ch * 8);
    }
    issue_kv(0, 0);
    CP_COMMIT();
    issue_kv(64, 1);
    CP_COMMIT();

    CP_WAIT1();          // Q + tile0 ready
    __syncthreads();

    uint32_t qf[2][4][4];
#pragma unroll
    for (int mi = 0; mi < 2; mi++)
#pragma unroll
        for (int kg = 0; kg < 4; kg++) {
            const int kw = kg * 8;
            qf[mi][kg][0] = Qs[(wrow + mi * 16 + r) * ST + kw + c];
            qf[mi][kg][1] = Qs[(wrow + mi * 16 + 8 + r) * ST + kw + c];
            qf[mi][kg][2] = Qs[(wrow + mi * 16 + r) * ST + kw + c + 4];
            qf[mi][kg][3] = Qs[(wrow + mi * 16 + 8 + r) * ST + kw + c + 4];
        }

    // ldmatrix B-fragment address components (same pattern as GEMM, proven)
    const int brow = ((lane >> 4) << 3) + (lane & 7);   // row within 16-group
    const int bwof = ((lane >> 3) & 1) << 2;            // word offset 0 or 4

    float m[4];
#pragma unroll
    for (int i = 0; i < 4; i++) m[i] = -1e30f;
    float O[2][9][4];   // [..][8] = l accumulator (ones column)
#pragma unroll
    for (int mi = 0; mi < 2; mi++)
#pragma unroll
        for (int ni = 0; ni < 9; ni++)
#pragma unroll
            for (int q = 0; q < 4; q++) O[mi][ni][q] = 0.0f;

    constexpr int NT = S_ / 64;   // 32 tiles
    for (int i = 0; i < NT; i++) {
        CP_WAIT1();              // tile i complete
        __syncthreads();         // the ONLY barrier this iteration
        if (i + 2 < NT) issue_kv((i + 2) * 64, (i + 2) % 3);
        CP_COMMIT();

        const int buf = i % 3;
        const uint32_t kb = ks_base + (buf * 64 * ST) * 4;
        const uint32_t vb = vs_base + (buf * 64 * ST) * 4;

        // S = Q @ K^T   (already in log2 domain: Q pre-scaled)
        float sf[2][8][4];
#pragma unroll
        for (int mi = 0; mi < 2; mi++)
#pragma unroll
            for (int ni = 0; ni < 8; ni++)
#pragma unroll
                for (int q = 0; q < 4; q++) sf[mi][ni][q] = 0.0f;
#pragma unroll
        for (int kg = 0; kg < 4; kg++) {
            const int kw = kg * 8;
            uint32_t bf[8][2];
#pragma unroll
            for (int p = 0; p < 4; p++) {
                uint32_t bq[4];
                ldsm4(bq, kb + ((p * 16 + brow) * ST + kw + bwof) * 4);
                bf[2 * p][0] = bq[0]; bf[2 * p][1] = bq[1];
                bf[2 * p + 1][0] = bq[2]; bf[2 * p + 1][1] = bq[3];
            }
#pragma unroll
            for (int ni = 0; ni < 8; ni++) {
                mma16(sf[0][ni], qf[0][kg], bf[ni][0], bf[ni][1]);
                mma16(sf[1][ni], qf[1][kg], bf[ni][0], bf[ni][1]);
            }
        }

        // log2-domain softmax -> fp16 P fragments directly
        uint32_t pf[2][4][4];
#pragma unroll
        for (int mi = 0; mi < 2; mi++) {
            float mloc0 = -1e30f, mloc1 = -1e30f;
#pragma unroll
            for (int ni = 0; ni < 8; ni++) {
                mloc0 = fmaxf(mloc0, fmaxf(sf[mi][ni][0], sf[mi][ni][1]));
                mloc1 = fmaxf(mloc1, fmaxf(sf[mi][ni][2], sf[mi][ni][3]));
            }
            mloc0 = fmaxf(mloc0, __shfl_xor_sync(0xffffffffu, mloc0, 1));
            mloc0 = fmaxf(mloc0, __shfl_xor_sync(0xffffffffu, mloc0, 2));
            mloc1 = fmaxf(mloc1, __shfl_xor_sync(0xffffffffu, mloc1, 1));
            mloc1 = fmaxf(mloc1, __shfl_xor_sync(0xffffffffu, mloc1, 2));

            const float mnew0 = fmaxf(m[mi * 2 + 0], mloc0);
            const float mnew1 = fmaxf(m[mi * 2 + 1], mloc1);
            const float alpha0 = exp2f(m[mi * 2 + 0] - mnew0);
            const float alpha1 = exp2f(m[mi * 2 + 1] - mnew1);
            m[mi * 2 + 0] = mnew0;
            m[mi * 2 + 1] = mnew1;

#pragma unroll
            for (int kg = 0; kg < 4; kg++) {
                pf[mi][kg][0] = ex2h2(packh2(sf[mi][2 * kg][0] - mnew0, sf[mi][2 * kg][1] - mnew0));
                pf[mi][kg][1] = ex2h2(packh2(sf[mi][2 * kg][2] - mnew1, sf[mi][2 * kg][3] - mnew1));
                pf[mi][kg][2] = ex2h2(packh2(sf[mi][2 * kg + 1][0] - mnew0, sf[mi][2 * kg + 1][1] - mnew0));
                pf[mi][kg][3] = ex2h2(packh2(sf[mi][2 * kg + 1][2] - mnew1, sf[mi][2 * kg + 1][3] - mnew1));
            }

#pragma unroll
            for (int ni = 0; ni < 9; ni++) {
                O[mi][ni][0] *= alpha0; O[mi][ni][1] *= alpha0;
                O[mi][ni][2] *= alpha1; O[mi][ni][3] *= alpha1;
            }
        }

        // O += P @ V  (ni=8 = ones column -> accumulates l)
#pragma unroll
        for (int kg = 0; kg < 4; kg++) {
            const int kw = kg * 8;
            uint32_t bf[8][2];
#pragma unroll
            for (int p = 0; p < 4; p++) {
                uint32_t bq[4];
                ldsm4(bq, vb + ((p * 16 + brow) * ST + kw + bwof) * 4);
                bf[2 * p][0] = bq[0]; bf[2 * p][1] = bq[1];
                bf[2 * p + 1][0] = bq[2]; bf[2 * p + 1][1] = bq[3];
            }
#pragma unroll
            for (int ni = 0; ni < 8; ni++) {
                mma16(O[0][ni], pf[0][kg], bf[ni][0], bf[ni][1]);
                mma16(O[1][ni], pf[1][kg], bf[ni][0], bf[ni][1]);
            }
            mma16(O[0][8], pf[0][kg], ones_b, ones_b);
            mma16(O[1][8], pf[1][kg], ones_b, ones_b);
        }
    }

    // Normalize (l lives in O[mi][8][0]/[2] of the c==0 lane of each quad)
#pragma unroll
    for (int mi = 0; mi < 2; mi++) {
        const float l0 = __shfl_sync(0xffffffffu, O[mi][8][0], lane & ~3);
        const float l1 = __shfl_sync(0xffffffffu, O[mi][8][2], lane & ~3);
        const float il0 = 1.0f / l0;
        const float il1 = 1.0f / l1;
#pragma unroll
        for (int ni = 0; ni < 8; ni++) {
            const int col = h * HD_ + ni * 8 + c2;
            const int row0 = q0 + wrow + mi * 16 + r;
            __half2 v0 = __floats2half2_rn(O[mi][ni][0] * il0, O[mi][ni][1] * il0);
            __half2 v1 = __floats2half2_rn(O[mi][ni][2] * il1, O[mi][ni][3] * il1);
            *reinterpret_cast<__half2*>(g_att + ((size_t)b * S_ + row0) * D_ + col)     = v0;
            *reinterpret_cast<__half2*>(g_att + ((size_t)b * S_ + row0 + 8) * D_ + col) = v1;
        }
    }
}

// ---------------------------------------------------------------------------
extern "C" void kernel_launch(void* const* d_in, const int* in_sizes, int n_in,
                              void* d_out, int out_size) {
    (void)in_sizes; (void)n_in; (void)out_size;
    const float* x     = (const float*)d_in[0];
    const float* Wqkv  = (const float*)d_in[1];
    const float* bqkv  = (const float*)d_in[2];
    const float* Wproj = (const float*)d_in[3];
    const float* bproj = (const float*)d_in[4];
    float* out = (float*)d_out;

    __half *xh_dev = nullptr, *att_dev = nullptr, *wqkvh_dev = nullptr, *wprojh_dev = nullptr;
    cudaGetSymbolAddress((void**)&xh_dev,     g_xh);
    cudaGetSymbolAddress((void**)&att_dev,    g_att);
    cudaGetSymbolAddress((void**)&wqkvh_dev,  g_wqkvh);
    cudaGetSymbolAddress((void**)&wprojh_dev, g_wprojh);

    // fp32 -> half converts (layout preserved; no transposes needed)
    {
        x2h_kernel<<<(int)(((size_t)B_ * S_ * D_) / 2048), 256>>>(x, xh_dev);
        x2h_kernel<<<(int)(((size_t)D_ * 3 * D_) / 2048), 256>>>(Wqkv, wqkvh_dev);
        x2h_kernel<<<(int)(((size_t)D_ * D_) / 2048), 256>>>(Wproj, wprojh_dev);
    }

    const int gemm_smem = 3 * (128 * 20 + 32 * 68) * 4;   // 56,832 B
    cudaFuncSetAttribute(mma_gemm_h<3 * D_, 0>, cudaFuncAttributeMaxDynamicSharedMemorySize, gemm_smem);
    cudaFuncSetAttribute(mma_gemm_h<D_, 1>,     cudaFuncAttributeMaxDynamicSharedMemorySize, gemm_smem);

    // QKV GEMM (128x128 tile, trans-B from [K,N] weights)
    {
        dim3 grid(3 * D_ / 128, (B_ * S_) / 128);
        mma_gemm_h<3 * D_, 0><<<grid, 128, gemm_smem>>>(xh_dev, wqkvh_dev, bqkv, nullptr);
    }

    // Attention (3-stage ring, one barrier/tile, ldmatrix K/V frags)
    {
        const int smem = (128 * 36 + 6 * 64 * 36) * 4;   // 73,728 B
        cudaFuncSetAttribute(attn_h, cudaFuncAttributeMaxDynamicSharedMemorySize, smem);
        dim3 grid(S_ / 128, H_, B_);
        attn_h<<<grid, 128, smem>>>();
    }

    // Output projection
    {
        dim3 grid(D_ / 128, (B_ * S_) / 128);
        mma_gemm_h<D_, 1><<<grid, 128, gemm_smem>>>(att_dev, wprojh_dev, bproj, out);
    }
}